// round 1
// baseline (speedup 1.0000x reference)
#include <cuda_runtime.h>
#include <math.h>

// ---------------------------------------------------------------------------
// IIDSegmentationLoss on GB300
//
// Stage 1: p[dy,dx,i,j] = sum_{n,y,x} A[n,i,y+dy-7,x+dx-7] * B[n,j,y,x]
//          (15x15 shifts, 10x10 channel pairs, zero-padded borders)
// Stage 2: scalar IID loss from the 225x10x10 joint histogram.
// ---------------------------------------------------------------------------

#define Tn      15            // shifts per axis
#define Kc      10            // channels
#define Hh      224
#define Ww      224
#define YT      8             // B rows per block
#define AROWS   (YT + 14)     // A rows incl. halo = 22
#define APITCH  240           // padded A row (x in [-7, 233))
#define IC      5             // i-channels per block (2 blocks cover k=10)
#define NBINS   (Tn*Tn*Kc*Kc) // 22500
#define NTASKS  (Tn*IC*2)     // 150 warp tasks per block: (dy, i, jgroup)

__device__ float g_p[NBINS];

// ---------------------------------------------------------------------------
__global__ void zero_p_kernel() {
    int t = blockIdx.x * blockDim.x + threadIdx.x;
    if (t < NBINS) g_p[t] = 0.0f;
}

// ---------------------------------------------------------------------------
// grid: (28 y-groups, 16 n, 2 i-halves), 256 threads.
// smem: A strip [IC][AROWS][APITCH] (zero-padded halo) + B strip [Kc][YT][Ww]
// Warp task (dy, i, jg): lanes index x; 15 dx accumulators x 5 j in registers.
// ---------------------------------------------------------------------------
__global__ __launch_bounds__(256) void corr_kernel(
    const float* __restrict__ A, const float* __restrict__ B)
{
    extern __shared__ float smem[];
    float* sA = smem;                         // IC*AROWS*APITCH = 26400 floats
    float* sB = smem + IC * AROWS * APITCH;   // Kc*YT*Ww        = 17920 floats

    const int yg = blockIdx.x;
    const int n  = blockIdx.y;
    const int ih = blockIdx.z;
    const int y0 = yg * YT;
    const int tid = threadIdx.x;

    // ---- stage A (with zero halo) ----
    const int atot = IC * AROWS * APITCH;
    for (int idx = tid; idx < atot; idx += 256) {
        int i    = idx / (AROWS * APITCH);
        int rest = idx % (AROWS * APITCH);
        int r    = rest / APITCH;
        int xx   = rest % APITCH;
        int gy   = y0 - 7 + r;
        int gx   = xx - 7;
        float v = 0.0f;
        if (gy >= 0 && gy < Hh && gx >= 0 && gx < Ww)
            v = A[(((size_t)n * Kc + ih * IC + i) * Hh + gy) * Ww + gx];
        sA[idx] = v;
    }
    // ---- stage B ----
    const int btot = Kc * YT * Ww;
    for (int idx = tid; idx < btot; idx += 256) {
        int j    = idx / (YT * Ww);
        int rest = idx % (YT * Ww);
        int yy   = rest / Ww;
        int x    = rest % Ww;
        sB[idx] = B[(((size_t)n * Kc + j) * Hh + (y0 + yy)) * Ww + x];
    }
    __syncthreads();

    const int w    = tid >> 5;
    const int lane = tid & 31;

    #pragma unroll 1
    for (int t = w; t < NTASKS; t += 8) {
        const int dy  = t / (IC * 2);
        const int rem = t % (IC * 2);
        const int i   = rem >> 1;
        const int jg  = rem & 1;

        float acc[Tn][5];
        #pragma unroll
        for (int d = 0; d < Tn; ++d)
            #pragma unroll
            for (int jj = 0; jj < 5; ++jj) acc[d][jj] = 0.0f;

        #pragma unroll 1
        for (int yy = 0; yy < YT; ++yy) {
            const float* arow = sA + (i * AROWS + yy + dy) * APITCH;
            const float* brow = sB + (jg * 5) * (YT * Ww) + yy * Ww;
            #pragma unroll
            for (int c = 0; c < 7; ++c) {
                const int x = c * 32 + lane;
                float b[5];
                #pragma unroll
                for (int jj = 0; jj < 5; ++jj) b[jj] = brow[jj * (YT * Ww) + x];
                float aw[Tn];
                #pragma unroll
                for (int d = 0; d < Tn; ++d) aw[d] = arow[x + d];
                #pragma unroll
                for (int d = 0; d < Tn; ++d)
                    #pragma unroll
                    for (int jj = 0; jj < 5; ++jj)
                        acc[d][jj] = fmaf(aw[d], b[jj], acc[d][jj]);
            }
        }

        // warp butterfly reduction over lanes (x partials)
        #pragma unroll
        for (int off = 16; off >= 1; off >>= 1)
            #pragma unroll
            for (int d = 0; d < Tn; ++d)
                #pragma unroll
                for (int jj = 0; jj < 5; ++jj)
                    acc[d][jj] += __shfl_xor_sync(0xffffffffu, acc[d][jj], off);

        if (lane == 0) {
            const int ig = ih * IC + i;
            #pragma unroll
            for (int d = 0; d < Tn; ++d)
                #pragma unroll
                for (int jj = 0; jj < 5; ++jj)
                    atomicAdd(&g_p[((dy * Tn + d) * Kc + ig) * Kc + jg * 5 + jj],
                              acc[d][jj]);
        }
    }
}

// ---------------------------------------------------------------------------
// Single-block loss kernel: exact transcription of the reference loss body.
// ---------------------------------------------------------------------------
__global__ void loss_kernel(float* __restrict__ out) {
    __shared__ float red[256];
    const int tid = threadIdx.x;

    // global min over p
    float m = 3.402823466e38f;
    for (int idx = tid; idx < NBINS; idx += 256) m = fminf(m, g_p[idx]);
    red[tid] = m;
    __syncthreads();
    for (int s = 128; s > 0; s >>= 1) {
        if (tid < s) red[tid] = fminf(red[tid], red[tid + s]);
        __syncthreads();
    }
    m = red[0];
    __syncthreads();

    float part = 0.0f;
    for (int t = tid; t < Tn * Tn; t += 256) {
        float v[Kc][Kc];
        float S = 0.0f;
        #pragma unroll
        for (int i = 0; i < Kc; ++i)
            #pragma unroll
            for (int j = 0; j < Kc; ++j) {
                float x = g_p[(t * Kc + i) * Kc + j] - m + 1e-16f;
                v[i][j] = x;
                S += x;
            }
        const float inv = 1.0f / S;

        // normalize + symmetrize in place
        #pragma unroll
        for (int i = 0; i < Kc; ++i) v[i][i] *= inv;
        #pragma unroll
        for (int i = 0; i < Kc; ++i)
            #pragma unroll
            for (int j = i + 1; j < Kc; ++j) {
                float s2 = 0.5f * (v[i][j] + v[j][i]) * inv;
                v[i][j] = s2;
                v[j][i] = s2;
            }

        float pi[Kc], pj[Kc];
        #pragma unroll
        for (int j = 0; j < Kc; ++j) pi[j] = 0.0f;
        #pragma unroll
        for (int i = 0; i < Kc; ++i) pj[i] = 0.0f;
        #pragma unroll
        for (int i = 0; i < Kc; ++i)
            #pragma unroll
            for (int j = 0; j < Kc; ++j) {
                pi[j] += v[i][j];
                pj[i] += v[i][j];
            }

        float l = 0.0f;
        #pragma unroll
        for (int i = 0; i < Kc; ++i)
            #pragma unroll
            for (int j = 0; j < Kc; ++j)
                l -= v[i][j] * (logf(v[i][j] + 1e-16f)
                                - logf(pi[j] + 1e-16f)
                                - logf(pj[i] + 1e-16f));
        part += l;
    }

    red[tid] = part;
    __syncthreads();
    for (int s = 128; s > 0; s >>= 1) {
        if (tid < s) red[tid] += red[tid + s];
        __syncthreads();
    }
    if (tid == 0) out[0] = red[0] / (float)(Tn * Tn);
}

// ---------------------------------------------------------------------------
extern "C" void kernel_launch(void* const* d_in, const int* in_sizes, int n_in,
                              void* d_out, int out_size)
{
    (void)in_sizes; (void)n_in; (void)out_size;
    const float* A = (const float*)d_in[0];   // x_out    (16,10,224,224) f32
    const float* B = (const float*)d_in[1];   // x_tf_out (16,10,224,224) f32
    float* out = (float*)d_out;

    const size_t smembytes = (size_t)(IC * AROWS * APITCH + Kc * YT * Ww) * sizeof(float);
    cudaFuncSetAttribute(corr_kernel,
                         cudaFuncAttributeMaxDynamicSharedMemorySize,
                         (int)smembytes);

    zero_p_kernel<<<(NBINS + 255) / 256, 256>>>();

    dim3 grid(Hh / YT, 16, 2);   // (28, 16, 2)
    corr_kernel<<<grid, 256, smembytes>>>(A, B);

    loss_kernel<<<1, 256>>>(out);
}

// round 2
// speedup vs baseline: 1.5477x; 1.5477x over previous
#include <cuda_runtime.h>
#include <math.h>

// ---------------------------------------------------------------------------
// IIDSegmentationLoss on GB300 — Round 2: packed fma.rn.f32x2 (FFMA2) inner loop
//
// Stage 1: p[dy,dx,i,j] = sum_{n,y,x} A[n,i,y+dy-7,x+dx-7] * B[n,j,y,x]
// Stage 2: scalar IID loss from the 225x10x10 joint histogram.
// ---------------------------------------------------------------------------

#define Tn      15            // shifts per axis
#define Kc      10            // channels
#define Hh      224
#define Ww      224
#define YT      8             // B rows per block
#define AROWS   (YT + 14)     // A rows incl. halo = 22
#define APITCH  240           // padded A row (x in [-7, 233))
#define IC      5             // i-channels per block (2 blocks cover k=10)
#define NBINS   (Tn*Tn*Kc*Kc) // 22500
#define NTASKS  (Tn*IC*2)     // 150 warp tasks per block: (dy, i, jgroup)
#define NP      8             // dx pairs: (0,1)(2,3)...(14,pad)

__device__ float g_p[NBINS];

// ---- packed f32x2 helpers (sm_100+) ----
#define FMA_F32X2(d, a, b, c) \
    asm("fma.rn.f32x2 %0, %1, %2, %3;" : "=l"(d) : "l"(a), "l"(b), "l"(c))
#define ADD_F32X2(d, a, b) \
    asm("add.rn.f32x2 %0, %1, %2;" : "=l"(d) : "l"(a), "l"(b))
#define PACK_F32X2(out, lo, hi) \
    asm("mov.b64 %0, {%1, %2};" : "=l"(out) : "f"(lo), "f"(hi))
#define UNPACK_F32X2(lo, hi, in) \
    asm("mov.b64 {%0, %1}, %2;" : "=f"(lo), "=f"(hi) : "l"(in))

// ---------------------------------------------------------------------------
__global__ void zero_p_kernel() {
    int t = blockIdx.x * blockDim.x + threadIdx.x;
    if (t < NBINS) g_p[t] = 0.0f;
}

// ---------------------------------------------------------------------------
// grid: (28 y-groups, 16 n, 2 i-halves), 256 threads.
// smem: A strip [IC][AROWS][APITCH] (zero halo) + B strip [Kc][YT][Ww]
// Warp task (dy, i, jg): lanes index x; 8 packed-dx accumulators x 5 j.
// ---------------------------------------------------------------------------
__global__ __launch_bounds__(256) void corr_kernel(
    const float* __restrict__ A, const float* __restrict__ B)
{
    extern __shared__ float smem[];
    float* sA = smem;                         // IC*AROWS*APITCH = 26400 floats
    float* sB = smem + IC * AROWS * APITCH;   // Kc*YT*Ww        = 17920 floats

    const int yg = blockIdx.x;
    const int n  = blockIdx.y;
    const int ih = blockIdx.z;
    const int y0 = yg * YT;
    const int tid = threadIdx.x;

    // ---- stage A (with zero halo) ----
    const int atot = IC * AROWS * APITCH;
    for (int idx = tid; idx < atot; idx += 256) {
        int i    = idx / (AROWS * APITCH);
        int rest = idx % (AROWS * APITCH);
        int r    = rest / APITCH;
        int xx   = rest % APITCH;
        int gy   = y0 - 7 + r;
        int gx   = xx - 7;
        float v = 0.0f;
        if (gy >= 0 && gy < Hh && gx >= 0 && gx < Ww)
            v = A[(((size_t)n * Kc + ih * IC + i) * Hh + gy) * Ww + gx];
        sA[idx] = v;
    }
    // ---- stage B ----
    const int btot = Kc * YT * Ww;
    for (int idx = tid; idx < btot; idx += 256) {
        int j    = idx / (YT * Ww);
        int rest = idx % (YT * Ww);
        int yy   = rest / Ww;
        int x    = rest % Ww;
        sB[idx] = B[(((size_t)n * Kc + j) * Hh + (y0 + yy)) * Ww + x];
    }
    __syncthreads();

    const int w    = tid >> 5;
    const int lane = tid & 31;

    #pragma unroll 1
    for (int t = w; t < NTASKS; t += 8) {
        const int dy  = t / (IC * 2);
        const int rem = t % (IC * 2);
        const int i   = rem >> 1;
        const int jg  = rem & 1;

        // acc[p][jj]: packed pair over (dx=2p, dx=2p+1); p=7 high half = pad
        unsigned long long acc[NP][5];
        #pragma unroll
        for (int p = 0; p < NP; ++p)
            #pragma unroll
            for (int jj = 0; jj < 5; ++jj) acc[p][jj] = 0ull;

        #pragma unroll 1
        for (int yy = 0; yy < YT; ++yy) {
            const float* arow = sA + (i * AROWS + yy + dy) * APITCH;
            const float* brow = sB + (jg * 5) * (YT * Ww) + yy * Ww;
            #pragma unroll
            for (int c = 0; c < 7; ++c) {
                const int x = c * 32 + lane;

                // B broadcast pairs
                unsigned long long bb[5];
                #pragma unroll
                for (int jj = 0; jj < 5; ++jj) {
                    float bv = brow[jj * (YT * Ww) + x];
                    PACK_F32X2(bb[jj], bv, bv);
                }
                // A window pairs: (arow[x+2p], arow[x+2p+1]); x+15 < APITCH ok
                unsigned long long ap[NP];
                #pragma unroll
                for (int p = 0; p < NP; ++p) {
                    float a0 = arow[x + 2 * p];
                    float a1 = arow[x + 2 * p + 1];
                    PACK_F32X2(ap[p], a0, a1);
                }
                #pragma unroll
                for (int p = 0; p < NP; ++p)
                    #pragma unroll
                    for (int jj = 0; jj < 5; ++jj)
                        FMA_F32X2(acc[p][jj], ap[p], bb[jj], acc[p][jj]);
            }
        }

        // warp butterfly reduction on packed values (both halves at once)
        #pragma unroll
        for (int off = 16; off >= 1; off >>= 1)
            #pragma unroll
            for (int p = 0; p < NP; ++p)
                #pragma unroll
                for (int jj = 0; jj < 5; ++jj) {
                    unsigned long long o =
                        __shfl_xor_sync(0xffffffffu, acc[p][jj], off);
                    ADD_F32X2(acc[p][jj], acc[p][jj], o);
                }

        if (lane == 0) {
            const int ig = ih * IC + i;
            #pragma unroll
            for (int p = 0; p < NP; ++p)
                #pragma unroll
                for (int jj = 0; jj < 5; ++jj) {
                    float lo, hi;
                    UNPACK_F32X2(lo, hi, acc[p][jj]);
                    int d0 = 2 * p;
                    atomicAdd(&g_p[((dy * Tn + d0) * Kc + ig) * Kc + jg * 5 + jj], lo);
                    if (p < NP - 1)
                        atomicAdd(&g_p[((dy * Tn + d0 + 1) * Kc + ig) * Kc + jg * 5 + jj], hi);
                }
        }
    }
}

// ---------------------------------------------------------------------------
// Single-block loss kernel: exact transcription of the reference loss body.
// ---------------------------------------------------------------------------
__global__ void loss_kernel(float* __restrict__ out) {
    __shared__ float red[256];
    const int tid = threadIdx.x;

    // global min over p
    float m = 3.402823466e38f;
    for (int idx = tid; idx < NBINS; idx += 256) m = fminf(m, g_p[idx]);
    red[tid] = m;
    __syncthreads();
    for (int s = 128; s > 0; s >>= 1) {
        if (tid < s) red[tid] = fminf(red[tid], red[tid + s]);
        __syncthreads();
    }
    m = red[0];
    __syncthreads();

    float part = 0.0f;
    for (int t = tid; t < Tn * Tn; t += 256) {
        float v[Kc][Kc];
        float S = 0.0f;
        #pragma unroll
        for (int i = 0; i < Kc; ++i)
            #pragma unroll
            for (int j = 0; j < Kc; ++j) {
                float x = g_p[(t * Kc + i) * Kc + j] - m + 1e-16f;
                v[i][j] = x;
                S += x;
            }
        const float inv = 1.0f / S;

        // normalize + symmetrize in place
        #pragma unroll
        for (int i = 0; i < Kc; ++i) v[i][i] *= inv;
        #pragma unroll
        for (int i = 0; i < Kc; ++i)
            #pragma unroll
            for (int j = i + 1; j < Kc; ++j) {
                float s2 = 0.5f * (v[i][j] + v[j][i]) * inv;
                v[i][j] = s2;
                v[j][i] = s2;
            }

        float pi[Kc], pj[Kc];
        #pragma unroll
        for (int j = 0; j < Kc; ++j) pi[j] = 0.0f;
        #pragma unroll
        for (int i = 0; i < Kc; ++i) pj[i] = 0.0f;
        #pragma unroll
        for (int i = 0; i < Kc; ++i)
            #pragma unroll
            for (int j = 0; j < Kc; ++j) {
                pi[j] += v[i][j];
                pj[i] += v[i][j];
            }

        float l = 0.0f;
        #pragma unroll
        for (int i = 0; i < Kc; ++i)
            #pragma unroll
            for (int j = 0; j < Kc; ++j)
                l -= v[i][j] * (logf(v[i][j] + 1e-16f)
                                - logf(pi[j] + 1e-16f)
                                - logf(pj[i] + 1e-16f));
        part += l;
    }

    red[tid] = part;
    __syncthreads();
    for (int s = 128; s > 0; s >>= 1) {
        if (tid < s) red[tid] += red[tid + s];
        __syncthreads();
    }
    if (tid == 0) out[0] = red[0] / (float)(Tn * Tn);
}

// ---------------------------------------------------------------------------
extern "C" void kernel_launch(void* const* d_in, const int* in_sizes, int n_in,
                              void* d_out, int out_size)
{
    (void)in_sizes; (void)n_in; (void)out_size;
    const float* A = (const float*)d_in[0];   // x_out    (16,10,224,224) f32
    const float* B = (const float*)d_in[1];   // x_tf_out (16,10,224,224) f32
    float* out = (float*)d_out;

    const size_t smembytes = (size_t)(IC * AROWS * APITCH + Kc * YT * Ww) * sizeof(float);
    cudaFuncSetAttribute(corr_kernel,
                         cudaFuncAttributeMaxDynamicSharedMemorySize,
                         (int)smembytes);

    zero_p_kernel<<<(NBINS + 255) / 256, 256>>>();

    dim3 grid(Hh / YT, 16, 2);   // (28, 16, 2)
    corr_kernel<<<grid, 256, smembytes>>>(A, B);

    loss_kernel<<<1, 256>>>(out);
}